// round 7
// baseline (speedup 1.0000x reference)
#include <cuda_runtime.h>
#include <cuda_bf16.h>

#define Bsz 8
#define Tsz 2048
#define Dsz 64
#define Fsz 128
#define NTILE 32              // Tsz/64 t-chunks per b
#define NBLK (NTILE * Bsz)    // 256 blocks total
#define LSP 68                // ls pitch (floats)
#define DTP 65                // dsT pitch (floats)

typedef unsigned long long u64;

// ---- scratch (allocation-free: __device__ globals) ----
__device__ float2 g_part[Bsz * Dsz * NTILE];   // per-(b,d,tile) (max, sumexp)
__device__ unsigned int g_bar;                 // monotonic barrier counter (zero-init)

// ---- packed f32x2 helpers ----
__device__ __forceinline__ u64 ffma2(u64 a, u64 b, u64 c) {
    u64 d;
    asm("fma.rn.f32x2 %0, %1, %2, %3;" : "=l"(d) : "l"(a), "l"(b), "l"(c));
    return d;
}
__device__ __forceinline__ u64 pk2(float x, float y) {
    u64 r;
    asm("mov.b64 %0, {%1, %2};" : "=l"(r) : "f"(x), "f"(y));
    return r;
}
__device__ __forceinline__ float2 upk2(u64 v) {
    float2 r;
    asm("mov.b64 {%0, %1}, %2;" : "=f"(r.x), "=f"(r.y) : "l"(v));
    return r;
}

// smem layout (floats)
#define XS_OFF   0                         // [64 t][128 f]
#define DST_OFF  (XS_OFF + 64 * 128)       // dsT [128 k][65]
#define LS_OFF   (DST_OFF + 128 * DTP)     // ls  [64 d][68 t]
#define XN_OFF   (LS_OFF + 64 * LSP)       // [64]
#define DN_OFF   (XN_OFF + 64)             // [64]
#define CS_OFF   (DN_OFF + 64)             // [64]
#define LSE_OFF  (CS_OFF + 64)             // [4]
#define WR_OFF   (LSE_OFF + 4)             // wred float2[8][64] = 1024 floats (8B aligned)
#define SM_FLOATS (WR_OFF + 1024)

__global__ void __launch_bounds__(256, 2)
lde_fused(const float* __restrict__ x, const float* __restrict__ dic,
          const float* __restrict__ wei, float* __restrict__ out) {
    extern __shared__ float sm[];
    float*  xs   = sm + XS_OFF;
    float*  dsT  = sm + DST_OFF;
    float*  ls   = sm + LS_OFF;
    float*  xn   = sm + XN_OFF;
    float*  dn   = sm + DN_OFF;
    float*  cs   = sm + CS_OFF;
    float*  lse  = sm + LSE_OFF;
    float2* wred = (float2*)(sm + WR_OFF);   // [warp][d]
    float2* mS   = (float2*)(sm + WR_OFF);   // reused post-barrier: [d] (M, invS)

    const int tid  = threadIdx.x;
    const int lane = tid & 31;
    const int warp = tid >> 5;
    const int tile = blockIdx.x;
    const int b    = blockIdx.y;
    const int t0   = tile * 64;

    // ---------------- prologue ----------------
    // x tile -> xs [t][f]
    {
        const float4* xg = (const float4*)(x + ((size_t)b * Tsz + t0) * Fsz);
        float4* xs4 = (float4*)xs;
        #pragma unroll
        for (int it = 0; it < 8; it++) {
            int fi = tid + it * 256;               // 2048 float4
            xs4[fi] = xg[fi];
        }
    }
    // dic -> dsT transposed [k][d]
    {
        const float4* dg4 = (const float4*)dic;    // fi4 = d*32 + kq
        #pragma unroll
        for (int it = 0; it < 8; it++) {
            int fi4 = tid + it * 256;
            int d = fi4 >> 5, kq = fi4 & 31;
            float4 v = dg4[fi4];
            dsT[(4 * kq + 0) * DTP + d] = v.x;
            dsT[(4 * kq + 1) * DTP + d] = v.y;
            dsT[(4 * kq + 2) * DTP + d] = v.z;
            dsT[(4 * kq + 3) * DTP + d] = v.w;
        }
    }
    // lse(wei) on warp 7
    if (warp == 7) {
        float a = wei[lane], bb = wei[lane + 32];
        float m = fmaxf(a, bb);
        #pragma unroll
        for (int off = 16; off > 0; off >>= 1)
            m = fmaxf(m, __shfl_xor_sync(0xffffffffu, m, off));
        float s = __expf(a - m) + __expf(bb - m);
        #pragma unroll
        for (int off = 16; off > 0; off >>= 1)
            s += __shfl_xor_sync(0xffffffffu, s, off);
        if (lane == 0) *lse = m + logf(s);
    }
    // out init by tile==0 blocks (before barrier -> ordered before all atomics)
    if (tile == 0) {
        const float4* dg4 = (const float4*)dic;
        float4* og4 = (float4*)(out + (size_t)b * (Dsz * Fsz));
        #pragma unroll
        for (int it = 0; it < 8; it++) {
            int fi = tid + it * 256;
            float4 v = dg4[fi];
            og4[fi] = make_float4(-v.x, -v.y, -v.z, -v.w);
        }
    }
    __syncthreads();

    // xn / dn / cs in parallel thread groups
    if (tid < 64) {
        const float4* xr = (const float4*)(xs + tid * 128);
        float s = 0.f;
        #pragma unroll
        for (int q = 0; q < 32; q++) {
            float4 v = xr[(q + tid) & 31];
            s += v.x * v.x + v.y * v.y + v.z * v.z + v.w * v.w;
        }
        xn[tid] = s;
    } else if (tid < 128) {
        int d = tid - 64;
        const float4* dr = (const float4*)(dic + d * Fsz);
        float s = 0.f;
        #pragma unroll
        for (int q = 0; q < 32; q++) {
            float4 v = dr[q];
            s += v.x * v.x + v.y * v.y + v.z * v.z + v.w * v.w;
        }
        dn[d] = s;
    } else if (tid < 192) {
        int d = tid - 128;
        cs[d] = -(wei[d] - *lse);
    }
    __syncthreads();

    // ---------------- phase 1: dist GEMM ----------------
    // warp owns t rows [8w, 8w+8); lane owns d = lane and lane+32.
    const int t0w = warp * 8;
    u64 acc0[8], acc1[8];
    #pragma unroll
    for (int i = 0; i < 8; i++) { acc0[i] = 0ull; acc1[i] = 0ull; }

    #pragma unroll 4
    for (int k = 0; k < 128; k += 4) {
        float b00 = dsT[(k + 0) * DTP + lane];
        float b01 = dsT[(k + 1) * DTP + lane];
        float b02 = dsT[(k + 2) * DTP + lane];
        float b03 = dsT[(k + 3) * DTP + lane];
        float b10 = dsT[(k + 0) * DTP + lane + 32];
        float b11 = dsT[(k + 1) * DTP + lane + 32];
        float b12 = dsT[(k + 2) * DTP + lane + 32];
        float b13 = dsT[(k + 3) * DTP + lane + 32];
        u64 B0a = pk2(b00, b01), B0b = pk2(b02, b03);
        u64 B1a = pk2(b10, b11), B1b = pk2(b12, b13);
        #pragma unroll
        for (int i = 0; i < 8; i++) {
            ulonglong2 av = *(const ulonglong2*)(xs + (t0w + i) * 128 + k);  // broadcast
            acc0[i] = ffma2(av.x, B0a, acc0[i]);
            acc0[i] = ffma2(av.y, B0b, acc0[i]);
            acc1[i] = ffma2(av.x, B1a, acc1[i]);
            acc1[i] = ffma2(av.y, B1b, acc1[i]);
        }
    }

    // epilogue: logits -> ls[d][t], per-(warp,d) softmax partials
    #pragma unroll
    for (int j = 0; j < 2; j++) {
        int d = lane + 32 * j;
        float cd = cs[d], dnd = dn[d];
        float lv[8];
        float m = -3.4e38f;
        #pragma unroll
        for (int i = 0; i < 8; i++) {
            float2 p = upk2(j ? acc1[i] : acc0[i]);
            float g = p.x + p.y;
            float d2 = fmaxf(xn[t0w + i] - 2.f * g + dnd, 0.f);
            lv[i] = cd * sqrtf(d2);
            m = fmaxf(m, lv[i]);
        }
        float s = 0.f;
        #pragma unroll
        for (int i = 0; i < 8; i++) {
            s += __expf(lv[i] - m);
            ls[d * LSP + t0w + i] = lv[i];
        }
        wred[warp * 64 + d] = make_float2(m, s);
    }
    __syncthreads();

    // combine 8 warps' partials per d -> g_part
    if (tid < 64) {
        float2 pr = wred[tid];
        float m = pr.x, s = pr.y;
        #pragma unroll
        for (int w = 1; w < 8; w++) {
            float2 p = wred[w * 64 + tid];
            float M = fmaxf(m, p.x);
            s = s * __expf(m - M) + p.y * __expf(p.x - M);
            m = M;
        }
        g_part[(b * Dsz + tid) * NTILE + tile] = make_float2(m, s);
    }
    __threadfence();
    __syncthreads();

    // ---------------- device-wide barrier (monotonic counter) ----------------
    if (tid == 0) {
        unsigned int old = atomicAdd(&g_bar, 1u);
        unsigned int target = (old / (unsigned)NBLK + 1u) * (unsigned)NBLK;
        volatile unsigned int* vb = &g_bar;
        while (*vb < target) __nanosleep(64);
        __threadfence();
    }
    __syncthreads();

    // ---------------- phase 2: output GEMM ----------------
    // combine per-tile partials -> (M, 1/S) per d for this b
    if (tid < 64) {
        const float2* pp = &g_part[(b * Dsz + tid) * NTILE];
        float2 p0 = pp[0];
        float M = p0.x;
        #pragma unroll
        for (int q = 1; q < NTILE; q++) M = fmaxf(M, pp[q].x);
        float S = 0.f;
        #pragma unroll
        for (int q = 0; q < NTILE; q++) { float2 p = pp[q]; S += p.y * __expf(p.x - M); }
        mS[tid] = make_float2(M, 1.f / S);
    }
    __syncthreads();

    // ls -> w in place
    {
        int d = tid >> 2, ts = (tid & 3) * 16;
        float2 ms = mS[d];
        float* lr = ls + d * LSP + ts;
        #pragma unroll
        for (int q = 0; q < 16; q++)
            lr[q] = __expf(lr[q] - ms.x) * ms.y;
    }
    __syncthreads();

    // GEMM2: warp owns d rows [8w, 8w+8); lane owns f pairs {2l} and {2l+64}.
    u64 acc[8][2];
    #pragma unroll
    for (int i = 0; i < 8; i++) { acc[i][0] = 0ull; acc[i][1] = 0ull; }

    #pragma unroll 2
    for (int t = 0; t < 64; t += 4) {
        u64 xa[4], xb[4];
        #pragma unroll
        for (int q = 0; q < 4; q++) {
            const u64* xr = (const u64*)(xs + (t + q) * 128);
            xa[q] = xr[lane];
            xb[q] = xr[lane + 32];
        }
        #pragma unroll
        for (int i = 0; i < 8; i++) {
            ulonglong2 wv = *(const ulonglong2*)(ls + (8 * warp + i) * LSP + t);  // broadcast
            float2 w01 = upk2(wv.x), w23 = upk2(wv.y);
            u64 s0 = pk2(w01.x, w01.x);
            u64 s1 = pk2(w01.y, w01.y);
            u64 s2 = pk2(w23.x, w23.x);
            u64 s3 = pk2(w23.y, w23.y);
            acc[i][0] = ffma2(s0, xa[0], acc[i][0]);
            acc[i][1] = ffma2(s0, xb[0], acc[i][1]);
            acc[i][0] = ffma2(s1, xa[1], acc[i][0]);
            acc[i][1] = ffma2(s1, xb[1], acc[i][1]);
            acc[i][0] = ffma2(s2, xa[2], acc[i][0]);
            acc[i][1] = ffma2(s2, xb[2], acc[i][1]);
            acc[i][0] = ffma2(s3, xa[3], acc[i][0]);
            acc[i][1] = ffma2(s3, xb[3], acc[i][1]);
        }
    }

    // epilogue: atomic accumulate into out
    {
        int f0 = 2 * lane;
        float* ob = out + (size_t)b * (Dsz * Fsz);
        #pragma unroll
        for (int i = 0; i < 8; i++) {
            int d = 8 * warp + i;
            float2 vA = upk2(acc[i][0]);
            float2 vB = upk2(acc[i][1]);
            float* o = ob + d * Fsz;
            atomicAdd(o + f0,      vA.x);
            atomicAdd(o + f0 + 1,  vA.y);
            atomicAdd(o + f0 + 64, vB.x);
            atomicAdd(o + f0 + 65, vB.y);
        }
    }
}

// ============================================================
extern "C" void kernel_launch(void* const* d_in, const int* in_sizes, int n_in,
                              void* d_out, int out_size) {
    const float* x   = (const float*)d_in[0];   // (8, 2048, 128)
    const float* dic = (const float*)d_in[1];   // (64, 128)
    const float* wei = (const float*)d_in[2];   // (64,)
    float* out = (float*)d_out;                 // (8, 8192)

    size_t smem = SM_FLOATS * sizeof(float);    // ~88 KB
    cudaFuncSetAttribute(lde_fused, cudaFuncAttributeMaxDynamicSharedMemorySize, (int)smem);
    lde_fused<<<dim3(NTILE, Bsz), 256, smem>>>(x, dic, wei, out);
}